// round 4
// baseline (speedup 1.0000x reference)
#include <cuda_runtime.h>
#include <cstdint>

#define NN 100000
#define NE 1600000
#define BN_EPS 1e-5f
#define SCAN_BLK 1024
#define NSB ((NN + SCAN_BLK - 1) / SCAN_BLK)   // 98

// ---------------- scratch ----------------
__device__ __align__(16) float g_hs [(size_t)NN * 128];   // h * dinv[row]
__device__ __align__(16) float g_agg[(size_t)NN * 128];   // aggregated + bias (pre-BN)
__device__ float g_dinv[NN];
__device__ int   g_deg [NN];
__device__ int   g_off [NN + 1];
__device__ int   g_cur [NN];
__device__ int   g_src [NE];
__device__ int   g_dst [NE];
__device__ int   g_esrc[NE];       // CSR: sources grouped by dst
__device__ int   g_bsum[NSB];
__device__ int   g_is64;
__device__ float g_stats[512];     // sum/sumsq: L1 [0:256), L2 [256:512)
__device__ float g_sc[512];        // scale/shift: L1 [0:256), L2 [256:512)

// ---------------- tf32 helpers ----------------
__device__ __forceinline__ uint32_t f2tf32(float v) {
    uint32_t r;
    asm("cvt.rna.tf32.f32 %0, %1;" : "=r"(r) : "f"(v));
    return r;
}
__device__ __forceinline__ void split_tf32(float v, uint32_t& hi, uint32_t& lo) {
    hi = f2tf32(v);
    lo = f2tf32(v - __uint_as_float(hi));
}
__device__ __forceinline__ void mma_tf32(float* c, const uint32_t* a, const uint32_t* b) {
    asm("mma.sync.aligned.m16n8k8.row.col.f32.tf32.tf32.f32 "
        "{%0,%1,%2,%3}, {%4,%5,%6,%7}, {%8,%9}, {%0,%1,%2,%3};"
        : "+f"(c[0]), "+f"(c[1]), "+f"(c[2]), "+f"(c[3])
        : "r"(a[0]), "r"(a[1]), "r"(a[2]), "r"(a[3]), "r"(b[0]), "r"(b[1]));
}

// ---------------- detect edge_index dtype (int64 vs int32) ----------------
__global__ void k_detect(const int* __restrict__ ei32) {
    int is64 = 1;
    for (int j = 0; j < 64; j++)
        if (ei32[2 * j + 1] != 0) { is64 = 0; break; }
    g_is64 = is64;
}

// ---------------- init: zero deg + stats ----------------
__global__ void k_init() {
    int i = blockIdx.x * blockDim.x + threadIdx.x;
    if (i < NN)  g_deg[i] = 0;
    if (i < 512) g_stats[i] = 0.f;
}

// ---------------- convert to int32 src/dst (clamped) + dst histogram ----------
__global__ void k_convert(const int* __restrict__ ei32) {
    int e = blockIdx.x * blockDim.x + threadIdx.x;
    if (e >= NE) return;
    int s, d;
    if (g_is64) {
        s = ei32[2 * (size_t)e];
        d = ei32[2 * ((size_t)NE + e)];
    } else {
        s = ei32[e];
        d = ei32[NE + e];
    }
    s = min(max(s, 0), NN - 1);
    d = min(max(d, 0), NN - 1);
    g_src[e] = s;
    g_dst[e] = d;
    atomicAdd(&g_deg[d], 1);
}

// ---------------- dinv = rsqrt(deg + 1) ----------------
__global__ void k_dinv() {
    int i = blockIdx.x * blockDim.x + threadIdx.x;
    if (i < NN) g_dinv[i] = rsqrtf((float)(g_deg[i] + 1));
}

// ---------------- scan stage 1: per-block sums ----------------
__global__ void k_bsum() {
    __shared__ int ws[8];
    int b = blockIdx.x, tid = threadIdx.x;
    int i = b * SCAN_BLK + tid * 4;
    int s = 0;
#pragma unroll
    for (int j = 0; j < 4; j++) { int idx = i + j; if (idx < NN) s += g_deg[idx]; }
#pragma unroll
    for (int o = 16; o; o >>= 1) s += __shfl_down_sync(~0u, s, o);
    if ((tid & 31) == 0) ws[tid >> 5] = s;
    __syncthreads();
    if (tid == 0) { int t = 0; for (int j = 0; j < 8; j++) t += ws[j]; g_bsum[b] = t; }
}

// ---------------- scan stage 2: exclusive scan of block sums ----------------
__global__ void k_scanb() {
    int run = 0;
    for (int i = 0; i < NSB; i++) { int t = g_bsum[i]; g_bsum[i] = run; run += t; }
    g_off[NN] = run;
}

// ---------------- scan stage 3: per-block exclusive scan -> offsets + cursor ----
__global__ void k_off() {
    __shared__ int wsum[8];
    int b = blockIdx.x, tid = threadIdx.x;
    int i0 = b * SCAN_BLK + tid * 4;
    int d0 = (i0 + 0 < NN) ? g_deg[i0 + 0] : 0;
    int d1 = (i0 + 1 < NN) ? g_deg[i0 + 1] : 0;
    int d2 = (i0 + 2 < NN) ? g_deg[i0 + 2] : 0;
    int d3 = (i0 + 3 < NN) ? g_deg[i0 + 3] : 0;
    int t = d0 + d1 + d2 + d3;
    int lane = tid & 31, w = tid >> 5;
    int v = t;
#pragma unroll
    for (int o = 1; o < 32; o <<= 1) { int u = __shfl_up_sync(~0u, v, o); if (lane >= o) v += u; }
    if (lane == 31) wsum[w] = v;
    __syncthreads();
    if (tid == 0) { int run = 0; for (int j = 0; j < 8; j++) { int x = wsum[j]; wsum[j] = run; run += x; } }
    __syncthreads();
    int excl = wsum[w] + (v - t) + g_bsum[b];
    int e0 = excl, e1 = e0 + d0, e2 = e1 + d1, e3 = e2 + d2;
    if (i0 + 0 < NN) { g_off[i0 + 0] = e0; g_cur[i0 + 0] = e0; }
    if (i0 + 1 < NN) { g_off[i0 + 1] = e1; g_cur[i0 + 1] = e1; }
    if (i0 + 2 < NN) { g_off[i0 + 2] = e2; g_cur[i0 + 2] = e2; }
    if (i0 + 3 < NN) { g_off[i0 + 3] = e3; g_cur[i0 + 3] = e3; }
}

// ---------------- bucket placement ----------------
__global__ void k_place() {
    int e = blockIdx.x * blockDim.x + threadIdx.x;
    if (e >= NE) return;
    int d = g_dst[e];
    int pos = atomicAdd(&g_cur[d], 1);
    g_esrc[pos] = g_src[e];
}

// =====================================================================
// Tensor-core SGEMM (tf32 3-term split): hs = act(A) @ W * dinv
// Block tile 128 x 128, BK=16, 8 warps as 4(m) x 2(n); warp = m32 x n64.
// =====================================================================
#define PADA 20
#define PADB 136
template <bool NORM>
__global__ void __launch_bounds__(256) k_gemm128(const float* __restrict__ Ain,
                                                 const float* __restrict__ W, int scOff) {
    const float* __restrict__ A = NORM ? g_agg : Ain;
    __shared__ uint32_t Ahi[128][PADA], Alo[128][PADA];
    __shared__ uint32_t Bhi[16][PADB],  Blo[16][PADB];
    __shared__ float sc_s[128], sh_s[128];

    const int tid = threadIdx.x;
    if (NORM) {
        if (tid < 128) {
            sc_s[tid] = g_sc[scOff + tid];
            sh_s[tid] = g_sc[scOff + 128 + tid];
        }
        __syncthreads();
    }

    const int row0 = blockIdx.x * 128;
    const int wid = tid >> 5, lane = tid & 31;
    const int wm = wid & 3, wn = wid >> 2;
    const int gr = lane >> 2, tg = lane & 3;

    float acc[2][8][4];
#pragma unroll
    for (int mt = 0; mt < 2; mt++)
#pragma unroll
        for (int nt = 0; nt < 8; nt++)
#pragma unroll
            for (int q = 0; q < 4; q++) acc[mt][nt][q] = 0.f;

    for (int kb = 0; kb < 128; kb += 16) {
        // load A tile (128 rows x 16 k), split hi/lo
#pragma unroll
        for (int i = 0; i < 2; i++) {
            int f = tid * 2 + i;          // 0..511
            int r = f >> 2;
            int c = (f & 3) * 4;
            float4 v = make_float4(0.f, 0.f, 0.f, 0.f);
            if (row0 + r < NN) v = *(const float4*)&A[(size_t)(row0 + r) * 128 + kb + c];
            if (NORM) {
                int ch = kb + c;
                v.x = fmaxf(fmaf(v.x, sc_s[ch + 0], sh_s[ch + 0]), 0.f);
                v.y = fmaxf(fmaf(v.y, sc_s[ch + 1], sh_s[ch + 1]), 0.f);
                v.z = fmaxf(fmaf(v.z, sc_s[ch + 2], sh_s[ch + 2]), 0.f);
                v.w = fmaxf(fmaf(v.w, sc_s[ch + 3], sh_s[ch + 3]), 0.f);
            }
            split_tf32(v.x, Ahi[r][c + 0], Alo[r][c + 0]);
            split_tf32(v.y, Ahi[r][c + 1], Alo[r][c + 1]);
            split_tf32(v.z, Ahi[r][c + 2], Alo[r][c + 2]);
            split_tf32(v.w, Ahi[r][c + 3], Alo[r][c + 3]);
        }
        // load W tile (16 k x 128 n), split hi/lo
#pragma unroll
        for (int i = 0; i < 2; i++) {
            int f = tid * 2 + i;
            int k = f >> 5;
            int c = (f & 31) * 4;
            float4 v = *(const float4*)&W[(size_t)(kb + k) * 128 + c];
            split_tf32(v.x, Bhi[k][c + 0], Blo[k][c + 0]);
            split_tf32(v.y, Bhi[k][c + 1], Blo[k][c + 1]);
            split_tf32(v.z, Bhi[k][c + 2], Blo[k][c + 2]);
            split_tf32(v.w, Bhi[k][c + 3], Blo[k][c + 3]);
        }
        __syncthreads();

#pragma unroll
        for (int ks = 0; ks < 16; ks += 8) {
            uint32_t a_hi[2][4], a_lo[2][4], b_hi[8][2], b_lo[8][2];
#pragma unroll
            for (int mt = 0; mt < 2; mt++) {
                int r = wm * 32 + mt * 16 + gr;
                a_hi[mt][0] = Ahi[r][ks + tg];     a_hi[mt][1] = Ahi[r + 8][ks + tg];
                a_hi[mt][2] = Ahi[r][ks + tg + 4]; a_hi[mt][3] = Ahi[r + 8][ks + tg + 4];
                a_lo[mt][0] = Alo[r][ks + tg];     a_lo[mt][1] = Alo[r + 8][ks + tg];
                a_lo[mt][2] = Alo[r][ks + tg + 4]; a_lo[mt][3] = Alo[r + 8][ks + tg + 4];
            }
#pragma unroll
            for (int nt = 0; nt < 8; nt++) {
                int c = wn * 64 + nt * 8 + gr;
                b_hi[nt][0] = Bhi[ks + tg][c]; b_hi[nt][1] = Bhi[ks + tg + 4][c];
                b_lo[nt][0] = Blo[ks + tg][c]; b_lo[nt][1] = Blo[ks + tg + 4][c];
            }
#pragma unroll
            for (int mt = 0; mt < 2; mt++)
#pragma unroll
                for (int nt = 0; nt < 8; nt++) {
                    mma_tf32(acc[mt][nt], a_hi[mt], b_hi[nt]);
                    mma_tf32(acc[mt][nt], a_hi[mt], b_lo[nt]);
                    mma_tf32(acc[mt][nt], a_lo[mt], b_hi[nt]);
                }
        }
        __syncthreads();
    }

    // epilogue: scale by dinv[row], write g_hs
#pragma unroll
    for (int mt = 0; mt < 2; mt++) {
        int rbase = row0 + wm * 32 + mt * 16 + gr;
#pragma unroll
        for (int h = 0; h < 2; h++) {
            int r = rbase + h * 8;
            if (r < NN) {
                float d = g_dinv[r];
#pragma unroll
                for (int nt = 0; nt < 8; nt++) {
                    int c = wn * 64 + nt * 8 + tg * 2;
                    float2 o;
                    o.x = acc[mt][nt][h * 2 + 0] * d;
                    o.y = acc[mt][nt][h * 2 + 1] * d;
                    *(float2*)&g_hs[(size_t)r * 128 + c] = o;
                }
            }
        }
    }
}

// ---------------- tensor-core GEMM, N=40 (layer 3), always NORM ----------------
__global__ void __launch_bounds__(256) k_gemm40(const float* __restrict__ W, int scOff) {
    const float* __restrict__ A = g_agg;
    __shared__ uint32_t Ahi[128][PADA], Alo[128][PADA];
    __shared__ uint32_t Bhi[16][40], Blo[16][40];
    __shared__ float sc_s[128], sh_s[128];

    const int tid = threadIdx.x;
    if (tid < 128) {
        sc_s[tid] = g_sc[scOff + tid];
        sh_s[tid] = g_sc[scOff + 128 + tid];
    }
    __syncthreads();

    const int row0 = blockIdx.x * 128;
    const int wid = tid >> 5, lane = tid & 31;
    const int gr = lane >> 2, tg = lane & 3;

    float acc[5][4];
#pragma unroll
    for (int nt = 0; nt < 5; nt++)
#pragma unroll
        for (int q = 0; q < 4; q++) acc[nt][q] = 0.f;

    for (int kb = 0; kb < 128; kb += 16) {
#pragma unroll
        for (int i = 0; i < 2; i++) {
            int f = tid * 2 + i;
            int r = f >> 2;
            int c = (f & 3) * 4;
            float4 v = make_float4(0.f, 0.f, 0.f, 0.f);
            if (row0 + r < NN) v = *(const float4*)&A[(size_t)(row0 + r) * 128 + kb + c];
            int ch = kb + c;
            v.x = fmaxf(fmaf(v.x, sc_s[ch + 0], sh_s[ch + 0]), 0.f);
            v.y = fmaxf(fmaf(v.y, sc_s[ch + 1], sh_s[ch + 1]), 0.f);
            v.z = fmaxf(fmaf(v.z, sc_s[ch + 2], sh_s[ch + 2]), 0.f);
            v.w = fmaxf(fmaf(v.w, sc_s[ch + 3], sh_s[ch + 3]), 0.f);
            split_tf32(v.x, Ahi[r][c + 0], Alo[r][c + 0]);
            split_tf32(v.y, Ahi[r][c + 1], Alo[r][c + 1]);
            split_tf32(v.z, Ahi[r][c + 2], Alo[r][c + 2]);
            split_tf32(v.w, Ahi[r][c + 3], Alo[r][c + 3]);
        }
        if (tid < 160) {
            int k = tid / 10;
            int c = (tid % 10) * 4;
            float4 v = *(const float4*)&W[(size_t)(kb + k) * 40 + c];
            split_tf32(v.x, Bhi[k][c + 0], Blo[k][c + 0]);
            split_tf32(v.y, Bhi[k][c + 1], Blo[k][c + 1]);
            split_tf32(v.z, Bhi[k][c + 2], Blo[k][c + 2]);
            split_tf32(v.w, Bhi[k][c + 3], Blo[k][c + 3]);
        }
        __syncthreads();

#pragma unroll
        for (int ks = 0; ks < 16; ks += 8) {
            uint32_t a_hi[4], a_lo[4], b_hi[5][2], b_lo[5][2];
            int r = wid * 16 + gr;
            a_hi[0] = Ahi[r][ks + tg];     a_hi[1] = Ahi[r + 8][ks + tg];
            a_hi[2] = Ahi[r][ks + tg + 4]; a_hi[3] = Ahi[r + 8][ks + tg + 4];
            a_lo[0] = Alo[r][ks + tg];     a_lo[1] = Alo[r + 8][ks + tg];
            a_lo[2] = Alo[r][ks + tg + 4]; a_lo[3] = Alo[r + 8][ks + tg + 4];
#pragma unroll
            for (int nt = 0; nt < 5; nt++) {
                int c = nt * 8 + gr;
                b_hi[nt][0] = Bhi[ks + tg][c]; b_hi[nt][1] = Bhi[ks + tg + 4][c];
                b_lo[nt][0] = Blo[ks + tg][c]; b_lo[nt][1] = Blo[ks + tg + 4][c];
            }
#pragma unroll
            for (int nt = 0; nt < 5; nt++) {
                mma_tf32(acc[nt], a_hi, b_hi[nt]);
                mma_tf32(acc[nt], a_hi, b_lo[nt]);
                mma_tf32(acc[nt], a_lo, b_hi[nt]);
            }
        }
        __syncthreads();
    }

#pragma unroll
    for (int h = 0; h < 2; h++) {
        int r = row0 + wid * 16 + gr + h * 8;
        if (r < NN) {
            float d = g_dinv[r];
#pragma unroll
            for (int nt = 0; nt < 5; nt++) {
                int c = nt * 8 + tg * 2;
                float2 o;
                o.x = acc[nt][h * 2 + 0] * d;
                o.y = acc[nt][h * 2 + 1] * d;
                *(float2*)&g_hs[(size_t)r * 40 + c] = o;
            }
        }
    }
}

// ---------------- CSR aggregate (C=128): warp per node + bias + BN stats ----
__global__ void __launch_bounds__(256) k_agg128(const float* __restrict__ bias, int statsOff) {
    __shared__ float sstat[256];
    int tid = threadIdx.x;
    sstat[tid] = 0.f;
    __syncthreads();

    int lane = tid & 31;
    int gw = (blockIdx.x * blockDim.x + tid) >> 5;
    int nw = (gridDim.x * blockDim.x) >> 5;
    float4 b = *(const float4*)&bias[lane * 4];
    float4 s1 = make_float4(0.f, 0.f, 0.f, 0.f);
    float4 s2 = make_float4(0.f, 0.f, 0.f, 0.f);

    for (int n = gw; n < NN; n += nw) {
        float4 acc = *(const float4*)&g_hs[(size_t)n * 128 + lane * 4];  // self loop
        int beg = g_off[n], end = g_off[n + 1];
        for (int i = beg; i < end; i++) {
            int s = g_esrc[i];
            float4 v = *(const float4*)&g_hs[(size_t)s * 128 + lane * 4];
            acc.x += v.x; acc.y += v.y; acc.z += v.z; acc.w += v.w;
        }
        float d = g_dinv[n];
        float4 val;
        val.x = fmaf(acc.x, d, b.x);
        val.y = fmaf(acc.y, d, b.y);
        val.z = fmaf(acc.z, d, b.z);
        val.w = fmaf(acc.w, d, b.w);
        *(float4*)&g_agg[(size_t)n * 128 + lane * 4] = val;
        s1.x += val.x; s1.y += val.y; s1.z += val.z; s1.w += val.w;
        s2.x += val.x * val.x; s2.y += val.y * val.y;
        s2.z += val.z * val.z; s2.w += val.w * val.w;
    }

    atomicAdd(&sstat[lane * 4 + 0], s1.x);
    atomicAdd(&sstat[lane * 4 + 1], s1.y);
    atomicAdd(&sstat[lane * 4 + 2], s1.z);
    atomicAdd(&sstat[lane * 4 + 3], s1.w);
    atomicAdd(&sstat[128 + lane * 4 + 0], s2.x);
    atomicAdd(&sstat[128 + lane * 4 + 1], s2.y);
    atomicAdd(&sstat[128 + lane * 4 + 2], s2.z);
    atomicAdd(&sstat[128 + lane * 4 + 3], s2.w);
    __syncthreads();
    atomicAdd(&g_stats[statsOff + tid], sstat[tid]);
}

// ---------------- CSR aggregate (C=40): direct output write ----------------------
__global__ void __launch_bounds__(256) k_agg40(const float* __restrict__ b3,
                                               float* __restrict__ out) {
    int tid = threadIdx.x;
    int lane = tid & 31;
    int gw = (blockIdx.x * blockDim.x + tid) >> 5;
    int nw = (gridDim.x * blockDim.x) >> 5;
    bool act = lane < 10;
    float4 b = make_float4(0.f, 0.f, 0.f, 0.f);
    if (act) b = *(const float4*)&b3[lane * 4];

    for (int n = gw; n < NN; n += nw) {
        int beg = g_off[n], end = g_off[n + 1];
        float4 acc = make_float4(0.f, 0.f, 0.f, 0.f);
        if (act) acc = *(const float4*)&g_hs[(size_t)n * 40 + lane * 4];
        for (int i = beg; i < end; i++) {
            int s = g_esrc[i];
            if (act) {
                float4 v = *(const float4*)&g_hs[(size_t)s * 40 + lane * 4];
                acc.x += v.x; acc.y += v.y; acc.z += v.z; acc.w += v.w;
            }
        }
        if (act) {
            float d = g_dinv[n];
            float4 o;
            o.x = fmaf(acc.x, d, b.x);
            o.y = fmaf(acc.y, d, b.y);
            o.z = fmaf(acc.z, d, b.z);
            o.w = fmaf(acc.w, d, b.w);
            *(float4*)&out[(size_t)n * 40 + lane * 4] = o;
        }
    }
}

// ---------------- finalize BN ----------------
__global__ void k_finalize(const float* __restrict__ gamma, const float* __restrict__ beta,
                           int statsOff, int scOff) {
    int c = threadIdx.x;            // 128 threads, 1 block
    float inv_n = 1.f / (float)NN;
    float mean = g_stats[statsOff + c] * inv_n;
    float var  = g_stats[statsOff + 128 + c] * inv_n - mean * mean;
    float inv  = rsqrtf(var + BN_EPS);
    float sc   = gamma[c] * inv;
    g_sc[scOff + c]       = sc;
    g_sc[scOff + 128 + c] = beta[c] - mean * sc;
}

// ---------------- launch ----------------
extern "C" void kernel_launch(void* const* d_in, const int* in_sizes, int n_in,
                              void* d_out, int out_size) {
    const float* x    = (const float*)d_in[0];
    const int*   ei32 = (const int*)d_in[1];
    const float* W1 = (const float*)d_in[2];
    const float* b1 = (const float*)d_in[3];
    const float* g1 = (const float*)d_in[4];
    const float* t1 = (const float*)d_in[5];
    const float* W2 = (const float*)d_in[6];
    const float* b2 = (const float*)d_in[7];
    const float* g2 = (const float*)d_in[8];
    const float* t2 = (const float*)d_in[9];
    const float* W3 = (const float*)d_in[10];
    const float* b3 = (const float*)d_in[11];
    float* out = (float*)d_out;

    const int gemmBlocks = (NN + 127) / 128;     // 782
    const int aggBlocks  = 1184;
    const int edgeBlocks = (NE + 255) / 256;     // 6250

    k_init<<<(NN + 255) / 256, 256>>>();
    k_detect<<<1, 1>>>(ei32);
    k_convert<<<edgeBlocks, 256>>>(ei32);
    k_dinv<<<(NN + 255) / 256, 256>>>();
    k_bsum<<<NSB, 256>>>();
    k_scanb<<<1, 1>>>();
    k_off<<<NSB, 256>>>();
    k_place<<<edgeBlocks, 256>>>();

    // layer 1
    k_gemm128<false><<<gemmBlocks, 256>>>(x, W1, 0);
    k_agg128<<<aggBlocks, 256>>>(b1, 0);
    k_finalize<<<1, 128>>>(g1, t1, 0, 0);

    // layer 2 (BN+ReLU fused into A-load)
    k_gemm128<true><<<gemmBlocks, 256>>>(nullptr, W2, 0);
    k_agg128<<<aggBlocks, 256>>>(b2, 256);
    k_finalize<<<1, 128>>>(g2, t2, 256, 256);

    // layer 3 (output, 40 cols)
    k_gemm40<<<gemmBlocks, 256>>>(W3, 256);
    k_agg40<<<aggBlocks, 256>>>(b3, out);
}